// round 9
// baseline (speedup 1.0000x reference)
#include <cuda_runtime.h>

// Single-pass IndRNN scan, decoupled lookback (aggregates + inclusives),
// with L2-resident re-read instead of a 32-register x buffer.
// h_t = relu(x_t + w*h_{t-1}), w >= 0. Chunk map g(h) = max(M, A + P*h).
// Phase 1 streams the chunk (U=8 pipeline) computing (M,A); phase 2 re-reads
// the same 16KB (hot in L2/L1) to emit. Registers drop ~57 -> ~38, lifting
// occupancy from 4 to 6-7 blocks/SM.

static constexpr int T     = 2048;
static constexpr int B     = 32;
static constexpr int H     = 1024;
static constexpr int BH    = B * H;        // 32768
static constexpr int L     = 32;           // timesteps per chunk
static constexpr int K     = T / L;        // 64 chunks
static constexpr int TILES = BH / 256;     // 128 channel tiles
static constexpr int NBLK  = TILES * K;    // 8192 blocks
static constexpr int U     = 8;            // load pipeline depth

// Slot per (k, c): {M, A, h, status}. status = 2*epoch (agg) | 2*epoch+1 (incl).
__device__ float4   g_slot[(size_t)K * BH];   // 32 MB
__device__ unsigned g_epoch;
__device__ unsigned g_ticket;

__global__ void k_prologue()
{
    g_epoch  = g_epoch + 1u;
    g_ticket = 0u;
}

__device__ __forceinline__ void st_slot(float4* p, float m, float a, float h,
                                        unsigned status)
{
    asm volatile("st.volatile.global.v4.f32 [%0], {%1, %2, %3, %4};"
                 :: "l"(p), "f"(m), "f"(a), "f"(h),
                    "f"(__uint_as_float(status)) : "memory");
}
__device__ __forceinline__ float4 ld_slot(const float4* p)
{
    float4 v;
    asm volatile("ld.volatile.global.v4.f32 {%0, %1, %2, %3}, [%4];"
                 : "=f"(v.x), "=f"(v.y), "=f"(v.z), "=f"(v.w) : "l"(p)
                 : "memory");
    return v;
}

__global__ __launch_bounds__(256, 6)
void indrnn_onepass(const float* __restrict__ x,
                    const float* __restrict__ h0,
                    const float* __restrict__ w,
                    float* __restrict__ out)
{
    __shared__ unsigned s_vid;
    if (threadIdx.x == 0) s_vid = atomicAdd(&g_ticket, 1u);
    __syncthreads();
    const unsigned vid = s_vid;
    const int tile = vid & (TILES - 1);
    const int k    = vid >> 7;                       // TILES = 128
    const int c    = tile * 256 + threadIdx.x;

    const unsigned epoch = g_epoch;
    const float wc  = __ldg(&w[c & (H - 1)]);
    const float h0c = __ldg(&h0[c]);
    float Pc = wc;
#pragma unroll
    for (int s = 0; s < 5; s++) Pc *= Pc;            // wc^32

    const float* const xbase = x + (size_t)k * L * BH + c;

    // ---- Phase 1: streaming aggregate (keeps x hot in L1/L2) ----
    float M = (wc > 0.0f) ? __int_as_float(0xff800000) : 0.0f;  // -inf / 0
    float A = 0.0f;
    {
        const float* xp = xbase;
        float buf[U];
#pragma unroll
        for (int i = 0; i < U; i++) buf[i] = xp[i * BH];
        for (int t0 = 0; t0 < L; t0 += U) {
            float nbuf[U];
            if (t0 + U < L) {
#pragma unroll
                for (int i = 0; i < U; i++) nbuf[i] = xp[(U + i) * BH];
            }
#pragma unroll
            for (int i = 0; i < U; i++) {
                M = fmaxf(0.0f, fmaf(wc, M, buf[i]));
                A = fmaf(wc, A, buf[i]);
            }
            xp += U * BH;
            if (t0 + U < L) {
#pragma unroll
                for (int i = 0; i < U; i++) buf[i] = nbuf[i];
            }
        }
    }

    // Publish aggregate IMMEDIATELY (independent of the chain).
    if (k < K - 1)
        st_slot(&g_slot[(size_t)k * BH + c], M, A, 0.0f, 2u * epoch);

    // Lookback: compose aggregates backward until an inclusive (or h0).
    float hin;
    if (k == 0) {
        hin = h0c;
    } else {
        float Ms = __int_as_float(0xff800000);       // identity map
        float As = 0.0f;
        float Ps = 1.0f;
        int   j  = k - 1;
        for (;;) {
            float4 s = ld_slot(&g_slot[(size_t)j * BH + c]);
            unsigned st = __float_as_uint(s.w);
            if (st == 2u * epoch + 1u) {             // inclusive h available
                hin = fmaxf(Ms, fmaf(Ps, s.z, As));
                break;
            }
            if (st == 2u * epoch) {                  // aggregate: compose
                const float nM = fmaxf(Ms, fmaf(Ps, s.x, As));
                As = fmaf(Ps, s.y, As);
                Ms = nM;
                Ps *= Pc;
                if (--j < 0) { hin = fmaxf(Ms, fmaf(Ps, h0c, As)); break; }
                continue;
            }
            __nanosleep(32);                         // predecessor not started
        }
    }

    // Publish inclusive (bounds lookback depth for later waves).
    if (k < K - 1) {
        const float hout = fmaxf(M, fmaf(Pc, hin, A));
        st_slot(&g_slot[(size_t)k * BH + c], M, A, hout, 2u * epoch + 1u);
    }

    // ---- Phase 2: emit; x re-read hits L1/L2 (loaded ~1us ago) ----
    {
        const float* xp = xbase;
        float* op = out + (size_t)k * L * BH + c;
        float h = hin;
        float buf[U];
#pragma unroll
        for (int i = 0; i < U; i++) buf[i] = xp[i * BH];
        for (int t0 = 0; t0 < L; t0 += U) {
            float nbuf[U];
            if (t0 + U < L) {
#pragma unroll
                for (int i = 0; i < U; i++) nbuf[i] = xp[(U + i) * BH];
            }
#pragma unroll
            for (int i = 0; i < U; i++) {
                h = fmaxf(fmaf(wc, h, buf[i]), 0.0f);
                __stcs(op + i * BH, h);
            }
            xp += U * BH;
            op += U * BH;
            if (t0 + U < L) {
#pragma unroll
                for (int i = 0; i < U; i++) buf[i] = nbuf[i];
            }
        }
    }
}

extern "C" void kernel_launch(void* const* d_in, const int* in_sizes, int n_in,
                              void* d_out, int out_size)
{
    const float* x  = (const float*)d_in[0];   // (T, B, H)
    const float* h0 = (const float*)d_in[1];   // (B, H)
    const float* w  = (const float*)d_in[2];   // (H,)
    float* out      = (float*)d_out;

    k_prologue<<<1, 1>>>();
    indrnn_onepass<<<NBLK, 256>>>(x, h0, w, out);
}

// round 11
// speedup vs baseline: 1.0382x; 1.0382x over previous
#include <cuda_runtime.h>

// Single-pass IndRNN scan, decoupled lookback. R7 register-buffer design
// (x read once into buf[32]) + slimmed publish protocol:
//  - 8-byte inclusive slot {epoch, h} (release/acquire), peeked FIRST;
//  - 16-byte aggregate slot published ONLY when the predecessor's inclusive
//    wasn't ready at peek time (slow path).
// h_t = relu(x_t + w*h_{t-1}), w >= 0. Chunk map g(h) = max(M, A + P*h).

static constexpr int T     = 2048;
static constexpr int B     = 32;
static constexpr int H     = 1024;
static constexpr int BH    = B * H;        // 32768
static constexpr int L     = 32;           // timesteps per chunk (registers)
static constexpr int K     = T / L;        // 64 chunks
static constexpr int TILES = BH / 256;     // 128 channel tiles
static constexpr int NBLK  = TILES * K;    // 8192 blocks

__device__ unsigned long long g_incl[(size_t)K * BH];  // {epoch<<32 | h bits}
__device__ float4             g_agg [(size_t)K * BH];  // {M, A, -, epoch}
__device__ unsigned           g_epoch;
__device__ unsigned           g_ticket;

__global__ void k_prologue()
{
    g_epoch  = g_epoch + 1u;   // stale slots (epoch-1 or 0) become invisible
    g_ticket = 0u;
}

__device__ __forceinline__ void st_release_u64(unsigned long long* p,
                                               unsigned long long v)
{
    asm volatile("st.release.gpu.global.u64 [%0], %1;" :: "l"(p), "l"(v) : "memory");
}
__device__ __forceinline__ unsigned long long ld_acquire_u64(
    const unsigned long long* p)
{
    unsigned long long v;
    asm volatile("ld.acquire.gpu.global.u64 %0, [%1];" : "=l"(v) : "l"(p) : "memory");
    return v;
}
__device__ __forceinline__ void st_agg(float4* p, float m, float a,
                                       unsigned status)
{
    asm volatile("st.volatile.global.v4.f32 [%0], {%1, %2, %3, %4};"
                 :: "l"(p), "f"(m), "f"(a), "f"(0.0f),
                    "f"(__uint_as_float(status)) : "memory");
}
__device__ __forceinline__ float4 ld_agg(const float4* p)
{
    float4 v;
    asm volatile("ld.volatile.global.v4.f32 {%0, %1, %2, %3}, [%4];"
                 : "=f"(v.x), "=f"(v.y), "=f"(v.z), "=f"(v.w) : "l"(p)
                 : "memory");
    return v;
}

__global__ __launch_bounds__(256)
void indrnn_onepass(const float* __restrict__ x,
                    const float* __restrict__ h0,
                    const float* __restrict__ w,
                    float* __restrict__ out)
{
    __shared__ unsigned s_vid;
    if (threadIdx.x == 0) s_vid = atomicAdd(&g_ticket, 1u);
    __syncthreads();
    const unsigned vid = s_vid;
    const int tile = vid & (TILES - 1);
    const int k    = vid >> 7;                       // TILES = 128
    const int c    = tile * 256 + threadIdx.x;

    const unsigned epoch = g_epoch;
    const float wc  = __ldg(&w[c & (H - 1)]);
    const float h0c = __ldg(&h0[c]);
    float Pc = wc;
#pragma unroll
    for (int s = 0; s < 5; s++) Pc *= Pc;            // wc^32

    const float* xp = x + (size_t)k * L * BH + c;

    // Load the whole chunk into registers (the only read of x).
    float buf[L];
#pragma unroll
    for (int i = 0; i < L; i++) buf[i] = __ldcs(xp + i * BH);

    // Early peek at predecessor's inclusive (overlaps with aggregate math).
    unsigned long long peek = 0;
    if (k > 0) peek = ld_acquire_u64(&g_incl[(size_t)(k - 1) * BH + c]);

    // Chunk aggregate: g(h) = max(M, A + Pc*h).
    float M = (wc > 0.0f) ? __int_as_float(0xff800000) : 0.0f;  // -inf / 0
    float A = 0.0f;
#pragma unroll
    for (int i = 0; i < L; i++) {
        M = fmaxf(0.0f, fmaf(wc, M, buf[i]));
        A = fmaf(wc, A, buf[i]);
    }

    float hin;
    if (k == 0) {
        hin = h0c;
    } else if ((unsigned)(peek >> 32) == epoch) {
        // Fast path: predecessor inclusive already there; no aggregate publish.
        hin = __uint_as_float((unsigned)peek);
    } else {
        // Slow path: publish our aggregate so consumers can pass over us,
        // then look back composing aggregates until an inclusive (or h0).
        st_agg(&g_agg[(size_t)k * BH + c], M, A, epoch);
        float Ms = __int_as_float(0xff800000);       // identity map
        float As = 0.0f;
        float Ps = 1.0f;
        int   j  = k - 1;
        for (;;) {
            unsigned long long v = ld_acquire_u64(&g_incl[(size_t)j * BH + c]);
            if ((unsigned)(v >> 32) == epoch) {      // inclusive available
                hin = fmaxf(Ms, fmaf(Ps, __uint_as_float((unsigned)v), As));
                break;
            }
            float4 s = ld_agg(&g_agg[(size_t)j * BH + c]);
            if (__float_as_uint(s.w) == epoch) {     // aggregate: compose
                const float nM = fmaxf(Ms, fmaf(Ps, s.x, As));
                As = fmaf(Ps, s.y, As);
                Ms = nM;
                Ps *= Pc;
                if (--j < 0) { hin = fmaxf(Ms, fmaf(Ps, h0c, As)); break; }
                continue;
            }
            __nanosleep(32);                         // j not started yet
        }
    }

    // Publish inclusive (single 8-byte release store).
    if (k < K - 1) {
        const float hout = fmaxf(M, fmaf(Pc, hin, A));
        st_release_u64(&g_incl[(size_t)k * BH + c],
                       ((unsigned long long)epoch << 32) | __float_as_uint(hout));
    }

    // Emit: exact forward recursion from registers.
    float* op = out + (size_t)k * L * BH + c;
    float h = hin;
#pragma unroll
    for (int i = 0; i < L; i++) {
        h = fmaxf(fmaf(wc, h, buf[i]), 0.0f);
        __stcs(op + i * BH, h);
    }
}

extern "C" void kernel_launch(void* const* d_in, const int* in_sizes, int n_in,
                              void* d_out, int out_size)
{
    const float* x  = (const float*)d_in[0];   // (T, B, H)
    const float* h0 = (const float*)d_in[1];   // (B, H)
    const float* w  = (const float*)d_in[2];   // (H,)
    float* out      = (float*)d_out;

    k_prologue<<<1, 1>>>();
    indrnn_onepass<<<NBLK, 256>>>(x, h0, w, out);
}

// round 14
// speedup vs baseline: 1.0779x; 1.0382x over previous
#include <cuda_runtime.h>

// Single-pass IndRNN scan, decoupled lookback (R7 protocol) + cp.async SMEM
// staging. h_t = relu(x_t + w*h_{t-1}), w >= 0.
// Chunk map g(h) = max(M, A + P*h), P = w^L, closed under composition.
// x is staged GMEM->SMEM via LDGSTS (no register buffer) so regs ~30 and
// 7 blocks/SM are resident; agg + emit both read SMEM.

static constexpr int T     = 2048;
static constexpr int B     = 32;
static constexpr int H     = 1024;
static constexpr int BH    = B * H;        // 32768
static constexpr int L     = 32;           // timesteps per chunk
static constexpr int K     = T / L;        // 64 chunks
static constexpr int TILES = BH / 256;     // 128 channel tiles
static constexpr int NBLK  = TILES * K;    // 8192 blocks
static constexpr int U     = 8;            // SMEM->reg prefetch depth

// Slot per (k, c): {M, A, h, status}; status = 2*epoch (agg) | 2*epoch+1 (incl).
__device__ float4   g_slot[(size_t)K * BH];   // 32 MB (L2-resident)
__device__ unsigned g_epoch;
__device__ unsigned g_ticket;

__global__ void k_prologue()
{
    g_epoch  = g_epoch + 1u;
    g_ticket = 0u;
}

__device__ __forceinline__ void st_slot(float4* p, float m, float a, float h,
                                        unsigned status)
{
    asm volatile("st.volatile.global.v4.f32 [%0], {%1, %2, %3, %4};"
                 :: "l"(p), "f"(m), "f"(a), "f"(h),
                    "f"(__uint_as_float(status)) : "memory");
}
__device__ __forceinline__ float4 ld_slot(const float4* p)
{
    float4 v;
    asm volatile("ld.volatile.global.v4.f32 {%0, %1, %2, %3}, [%4];"
                 : "=f"(v.x), "=f"(v.y), "=f"(v.z), "=f"(v.w) : "l"(p)
                 : "memory");
    return v;
}

__global__ __launch_bounds__(256)
void indrnn_onepass(const float* __restrict__ x,
                    const float* __restrict__ h0,
                    const float* __restrict__ w,
                    float* __restrict__ out)
{
    __shared__ float    sx[L][256];           // 32 KB staged x
    __shared__ unsigned s_vid;
    if (threadIdx.x == 0) s_vid = atomicAdd(&g_ticket, 1u);
    __syncthreads();
    const unsigned vid = s_vid;
    const int tile = vid & (TILES - 1);
    const int k    = vid >> 7;                // TILES = 128
    const int tid  = threadIdx.x;
    const int c    = tile * 256 + tid;

    const unsigned epoch = g_epoch;
    const float wc  = __ldg(&w[c & (H - 1)]);
    const float h0c = __ldg(&h0[c]);
    float Pc = wc;
#pragma unroll
    for (int s = 0; s < 5; s++) Pc *= Pc;     // wc^32

    // ---- Stage chunk GMEM -> SMEM via cp.async (16B per op, L1-bypass) ----
    // 32 KB = 2048 x 16B chunks; 8 per thread. chunk -> (t, 16B-col).
    {
        const float* gbase = x + (size_t)k * L * BH + tile * 256;
#pragma unroll
        for (int r = 0; r < 8; r++) {
            const int idx   = r * 256 + tid;
            const int t     = idx >> 6;              // 64 chunks per row
            const int col16 = idx & 63;
            const float* src = gbase + (size_t)t * BH + col16 * 4;
            unsigned dst = (unsigned)__cvta_generic_to_shared(&sx[t][col16 * 4]);
            asm volatile("cp.async.cg.shared.global [%0], [%1], 16;"
                         :: "r"(dst), "l"(src) : "memory");
        }
        asm volatile("cp.async.commit_group;" ::: "memory");
        asm volatile("cp.async.wait_group 0;" ::: "memory");
    }
    __syncthreads();

    // ---- Chunk aggregate from SMEM: g(h) = max(M, A + Pc*h) ----
    float M = (wc > 0.0f) ? __int_as_float(0xff800000) : 0.0f;  // -inf / 0
    float A = 0.0f;
    {
        float buf[U];
#pragma unroll
        for (int i = 0; i < U; i++) buf[i] = sx[i][tid];
#pragma unroll
        for (int t0 = 0; t0 < L; t0 += U) {
            float nbuf[U];
            if (t0 + U < L) {
#pragma unroll
                for (int i = 0; i < U; i++) nbuf[i] = sx[t0 + U + i][tid];
            }
#pragma unroll
            for (int i = 0; i < U; i++) {
                M = fmaxf(0.0f, fmaf(wc, M, buf[i]));
                A = fmaf(wc, A, buf[i]);
            }
#pragma unroll
            for (int i = 0; i < U; i++) buf[i] = nbuf[i];
        }
    }

    // ---- Acquire h_in (fast path: predecessor inclusive already visible) ----
    float hin;
    if (k == 0) {
        hin = h0c;
    } else {
        float4 p = ld_slot(&g_slot[(size_t)(k - 1) * BH + c]);
        if (__float_as_uint(p.w) == 2u * epoch + 1u) {
            hin = p.z;                              // no agg publish needed
        } else {
            // Slow path: publish aggregate, then compose backwards.
            st_slot(&g_slot[(size_t)k * BH + c], M, A, 0.0f, 2u * epoch);
            float Ms = __int_as_float(0xff800000);
            float As = 0.0f;
            float Ps = 1.0f;
            int   j  = k - 1;
            for (;;) {
                float4 s = ld_slot(&g_slot[(size_t)j * BH + c]);
                unsigned st = __float_as_uint(s.w);
                if (st == 2u * epoch + 1u) {        // inclusive
                    hin = fmaxf(Ms, fmaf(Ps, s.z, As));
                    break;
                }
                if (st == 2u * epoch) {             // aggregate: compose
                    const float nM = fmaxf(Ms, fmaf(Ps, s.x, As));
                    As = fmaf(Ps, s.y, As);
                    Ms = nM;
                    Ps *= Pc;
                    if (--j < 0) { hin = fmaxf(Ms, fmaf(Ps, h0c, As)); break; }
                    continue;
                }
                __nanosleep(32);
            }
        }
    }

    // ---- Publish inclusive ----
    if (k < K - 1) {
        const float hout = fmaxf(M, fmaf(Pc, hin, A));
        st_slot(&g_slot[(size_t)k * BH + c], M, A, hout, 2u * epoch + 1u);
    }

    // ---- Emit from SMEM ----
    {
        float* op = out + (size_t)k * L * BH + c;
        float h = hin;
        float buf[U];
#pragma unroll
        for (int i = 0; i < U; i++) buf[i] = sx[i][tid];
#pragma unroll
        for (int t0 = 0; t0 < L; t0 += U) {
            float nbuf[U];
            if (t0 + U < L) {
#pragma unroll
                for (int i = 0; i < U; i++) nbuf[i] = sx[t0 + U + i][tid];
            }
#pragma unroll
            for (int i = 0; i < U; i++) {
                h = fmaxf(fmaf(wc, h, buf[i]), 0.0f);
                __stcs(op + (size_t)(t0 + i) * BH, h);
            }
#pragma unroll
            for (int i = 0; i < U; i++) buf[i] = nbuf[i];
        }
    }
}

extern "C" void kernel_launch(void* const* d_in, const int* in_sizes, int n_in,
                              void* d_out, int out_size)
{
    const float* x  = (const float*)d_in[0];   // (T, B, H)
    const float* h0 = (const float*)d_in[1];   // (B, H)
    const float* w  = (const float*)d_in[2];   // (H,)
    float* out      = (float*)d_out;

    k_prologue<<<1, 1>>>();
    indrnn_onepass<<<NBLK, 256>>>(x, h0, w, out);
}